// round 14
// baseline (speedup 1.0000x reference)
#include <cuda_runtime.h>
#include <cstdint>

#define BATCH    64
#define SEQ      8192
#define RDIM     80
#define NSLOT    264           // 256-slot ring + 8 mirror slots (dup of 0..7)
#define CHUNK    8
#define NTHREADS 416           // warps 0-9: X (old-tap producers), 10-12: Y
#define NX       320

typedef unsigned long long u64;

__device__ __forceinline__ u64 ffma2(u64 a, u64 b, u64 c) {
    u64 d;
    asm("fma.rn.f32x2 %0, %1, %2, %3;" : "=l"(d) : "l"(a), "l"(b), "l"(c));
    return d;
}
__device__ __forceinline__ u64 fadd2(u64 a, u64 b) {
    u64 d;
    asm("add.rn.f32x2 %0, %1, %2;" : "=l"(d) : "l"(a), "l"(b));
    return d;
}
__device__ __forceinline__ float2 unpack2(u64 v) {
    unsigned lo, hi;
    asm("mov.b64 {%0, %1}, %2;" : "=r"(lo), "=r"(hi) : "l"(v));
    float2 r; r.x = __uint_as_float(lo); r.y = __uint_as_float(hi);
    return r;
}
__device__ __forceinline__ float fast_tanh(float v) {
    v = fminf(fmaxf(v, -15.0f), 15.0f);
    float u = __expf(-2.0f * v);
    return __fdividef(1.0f - u, 1.0f + u);
}

// One 20-MAC tap slice using weights W[0..9] at an immediate-offset address
#define TAP_ACC(W, ptr)                                                   \
    do {                                                                  \
        const ulonglong2* hv = reinterpret_cast<const ulonglong2*>(ptr);  \
        ulonglong2 h01 = hv[0];                                           \
        ulonglong2 h23 = hv[1];                                           \
        ulonglong2 h45 = hv[2];                                           \
        ulonglong2 h67 = hv[3];                                           \
        ulonglong2 h89 = hv[4];                                           \
        a0 = ffma2(h01.x, (W)[0], a0);                                    \
        a1 = ffma2(h01.y, (W)[1], a1);                                    \
        a2 = ffma2(h23.x, (W)[2], a2);                                    \
        a3 = ffma2(h23.y, (W)[3], a3);                                    \
        a0 = ffma2(h45.x, (W)[4], a0);                                    \
        a1 = ffma2(h45.y, (W)[5], a1);                                    \
        a2 = ffma2(h67.x, (W)[6], a2);                                    \
        a3 = ffma2(h67.y, (W)[7], a3);                                    \
        a0 = ffma2(h89.x, (W)[8], a0);                                    \
        a1 = ffma2(h89.y, (W)[9], a1);                                    \
    } while (0)

// Full 80-MAC row (20 LDS.128 broadcasts, 40 FFMA2, 4 chains)
__device__ __forceinline__ float row_dot(const u64* W, const float* hrow) {
    const ulonglong2* hv = reinterpret_cast<const ulonglong2*>(hrow);
    u64 a0 = 0ull, a1 = 0ull, a2 = 0ull, a3 = 0ull;
#pragma unroll
    for (int p = 0; p < 10; p++) {
        ulonglong2 A = hv[2 * p];
        ulonglong2 B = hv[2 * p + 1];
        a0 = ffma2(A.x, W[4 * p + 0], a0);
        a1 = ffma2(A.y, W[4 * p + 1], a1);
        a2 = ffma2(B.x, W[4 * p + 2], a2);
        a3 = ffma2(B.y, W[4 * p + 3], a3);
    }
    float2 r = unpack2(fadd2(fadd2(a0, a1), fadd2(a2, a3)));
    return r.x + r.y;
}

__global__ __launch_bounds__(NTHREADS, 1)
void reservoir_kernel(const float* __restrict__ x,
                      const float* __restrict__ Win,
                      const float* __restrict__ Wfb,
                      const float* __restrict__ bias,
                      float* __restrict__ out)
{
    extern __shared__ float sm[];
    float* Hring = sm;                      // [NSLOT][RDIM] = 21120 f
    float* xs    = Hring + NSLOT * RDIM;    // [SEQ]         = 8192 f
    float* part  = xs + SEQ;                // [4][320]  part[buf][i*4+jh]

    const int b   = blockIdx.x;
    const int tid = threadIdx.x;

    const bool isY  = (tid >= NX);
    // X identity
    const int xi  = isY ? 0 : (tid % RDIM);
    const int xjh = isY ? 0 : (tid / RDIM);
    // Y identity
    const int yi   = isY ? (tid - NX) : 0;       // 0..95
    const bool yact = isY && (yi < RDIM);

    for (int idx = tid; idx < NSLOT * RDIM; idx += NTHREADS) Hring[idx] = 0.0f;
    for (int idx = tid; idx < 4 * NX; idx += NTHREADS) part[idx] = 0.0f;
    const float* xb = x + (size_t)b * SEQ;
    for (int idx = tid; idx < SEQ; idx += NTHREADS) xs[idx] = xb[idx];

    // Weights: X packs 4 old-tap slices (4 x 10 pairs); Y packs tau=1 row (40 pairs)
    u64 W[40];
    if (!isY) {
#pragma unroll
        for (int k = 0; k < 4; k++) {
            const float* wrow =
                Wfb + ((size_t)(k + 1) * RDIM + xi) * RDIM + xjh * 20;
#pragma unroll
            for (int p = 0; p < 10; p++) {
                unsigned lo = __float_as_uint(wrow[2 * p]);
                unsigned hi = __float_as_uint(wrow[2 * p + 1]);
                W[k * 10 + p] = ((u64)hi << 32) | (u64)lo;
            }
        }
    } else if (yact) {
        const float* wrow = Wfb + (size_t)yi * RDIM;
#pragma unroll
        for (int p = 0; p < 40; p++) {
            unsigned lo = __float_as_uint(wrow[2 * p]);
            unsigned hi = __float_as_uint(wrow[2 * p + 1]);
            W[p] = ((u64)hi << 32) | (u64)lo;
        }
    }

    float win_i = 0.0f, bias_i = 0.0f, h_i = 0.0f;
    if (yact) { win_i = Win[yi]; bias_i = bias[yi]; }

    float* outb = out + (size_t)b * SEQ * RDIM;

    __syncthreads();

#pragma unroll 1
    for (int T = 0; T < SEQ; T += CHUNK) {
        // Chunk-base pointers (only ring math); per-step addrs are immediates.
        // All bases <= 255; base+7 <= 262 is covered by mirror slots 256..263.
        const float* pX0 = Hring + ((unsigned)(T - 1)   & 255u) * RDIM + xjh * 20; // tau4  -> h[t-1]
        const float* pX1 = Hring + ((unsigned)(T - 21)  & 255u) * RDIM + xjh * 20; // tau24 -> h[t-21]
        const float* pX2 = Hring + ((unsigned)(T - 93)  & 255u) * RDIM + xjh * 20; // tau96 -> h[t-93]
        const float* pX3 = Hring + ((unsigned)(T - 165) & 255u) * RDIM + xjh * 20; // tau168-> h[t-165]
        const float* hY  = Hring + ((unsigned)(T - 1)   & 255u) * RDIM;            // h[t-1]
        const int   W0   = T & 255;
        float*      hw   = Hring + W0 * RDIM + yi;
        const bool  mirror = (W0 == 0);
        float*      op   = outb + (size_t)T * RDIM + yi;
        const float* xp  = xs + T;

#pragma unroll
        for (int s = 0; s < CHUNK; ++s) {
            if (!isY) {
                // ==== X: old-tap partials for step t+3 (t = T+s) ====
                u64 a0 = 0ull, a1 = 0ull, a2 = 0ull, a3 = 0ull;
                TAP_ACC(W +  0, pX0 + s * RDIM);
                TAP_ACC(W + 10, pX1 + s * RDIM);
                TAP_ACC(W + 20, pX2 + s * RDIM);
                TAP_ACC(W + 30, pX3 + s * RDIM);
                float2 r = unpack2(fadd2(fadd2(a0, a1), fadd2(a2, a3)));
                part[((s + 3) & 3) * NX + xi * 4 + xjh] = r.x + r.y;
            } else if (yact) {
                // ==== Y: tau=1 full row + update (critical path) ====
                float dot = row_dot(W, hY + s * RDIM);
                float4 P = *reinterpret_cast<const float4*>(
                    part + (s & 3) * NX + yi * 4);
                float f   = dot + ((P.x + P.y) + (P.z + P.w));
                float val = fmaf(xp[s], win_i, f + bias_i);
                h_i = 0.7f * h_i + 0.3f * fast_tanh(val);
                hw[s * RDIM] = h_i;                       // slot W0+s
                if (mirror) hw[(256 + s) * RDIM] = h_i;   // mirror 256..263
                op[(size_t)s * RDIM] = h_i;
            }
            // Single barrier: publishes h[t] (Y) and partials(t+3) (X).
            __syncthreads();
        }
    }
}

extern "C" void kernel_launch(void* const* d_in, const int* in_sizes, int n_in,
                              void* d_out, int out_size)
{
    const float* x    = (const float*)d_in[0];  // [64, 8192, 1]
    const float* Win  = (const float*)d_in[1];  // [80, 1]
    const float* Wfb  = (const float*)d_in[2];  // [5, 80, 80]
    const float* bias = (const float*)d_in[3];  // [80]
    float* out = (float*)d_out;                 // [64, 8192, 80]

    const int smem_bytes = (NSLOT * RDIM + SEQ + 4 * NX) * sizeof(float);
    cudaFuncSetAttribute(reservoir_kernel,
                         cudaFuncAttributeMaxDynamicSharedMemorySize, smem_bytes);

    reservoir_kernel<<<BATCH, NTHREADS, smem_bytes>>>(x, Win, Wfb, bias, out);
}

// round 15
// speedup vs baseline: 1.2272x; 1.2272x over previous
#include <cuda_runtime.h>
#include <cstdint>

#define BATCH    64
#define SEQ      8192
#define RDIM     80
#define NSLOT    264           // 256-slot ring + 8 mirror slots (dup of 0..7)
#define CHUNK    8
#define NTHREADS 416           // warps 0-9: producers (320), 10-12: epilogue (96)
#define NX       320

typedef unsigned long long u64;

__device__ __forceinline__ u64 ffma2(u64 a, u64 b, u64 c) {
    u64 d;
    asm("fma.rn.f32x2 %0, %1, %2, %3;" : "=l"(d) : "l"(a), "l"(b), "l"(c));
    return d;
}
__device__ __forceinline__ u64 fadd2(u64 a, u64 b) {
    u64 d;
    asm("add.rn.f32x2 %0, %1, %2;" : "=l"(d) : "l"(a), "l"(b));
    return d;
}
__device__ __forceinline__ float2 unpack2(u64 v) {
    unsigned lo, hi;
    asm("mov.b64 {%0, %1}, %2;" : "=r"(lo), "=r"(hi) : "l"(v));
    float2 r; r.x = __uint_as_float(lo); r.y = __uint_as_float(hi);
    return r;
}
__device__ __forceinline__ float fast_tanh(float v) {
    v = fminf(fmaxf(v, -15.0f), 15.0f);
    float u = __expf(-2.0f * v);
    return __fdividef(1.0f - u, 1.0f + u);
}

// Barrier A (id 1): epilogue arrives (publishes h[t]), producers sync.
// Barrier B (id 2): producers arrive (publish partials), epilogue syncs.
#define BAR_SYNC_A()   asm volatile("bar.sync 1, %0;"   :: "n"(NTHREADS) : "memory")
#define BAR_ARRIVE_A() asm volatile("bar.arrive 1, %0;" :: "n"(NTHREADS) : "memory")
#define BAR_SYNC_B()   asm volatile("bar.sync 2, %0;"   :: "n"(NTHREADS) : "memory")
#define BAR_ARRIVE_B() asm volatile("bar.arrive 2, %0;" :: "n"(NTHREADS) : "memory")

// One 20-MAC tap slice at an immediate-offset address
#define TAP_ACC(W, ptr)                                                   \
    do {                                                                  \
        const ulonglong2* hv = reinterpret_cast<const ulonglong2*>(ptr);  \
        ulonglong2 h01 = hv[0];                                           \
        ulonglong2 h23 = hv[1];                                           \
        ulonglong2 h45 = hv[2];                                           \
        ulonglong2 h67 = hv[3];                                           \
        ulonglong2 h89 = hv[4];                                           \
        a0 = ffma2(h01.x, (W)[0], a0);                                    \
        a1 = ffma2(h01.y, (W)[1], a1);                                    \
        a2 = ffma2(h23.x, (W)[2], a2);                                    \
        a3 = ffma2(h23.y, (W)[3], a3);                                    \
        a0 = ffma2(h45.x, (W)[4], a0);                                    \
        a1 = ffma2(h45.y, (W)[5], a1);                                    \
        a2 = ffma2(h67.x, (W)[6], a2);                                    \
        a3 = ffma2(h67.y, (W)[7], a3);                                    \
        a0 = ffma2(h89.x, (W)[8], a0);                                    \
        a1 = ffma2(h89.y, (W)[9], a1);                                    \
    } while (0)

__global__ __launch_bounds__(NTHREADS, 1)
void reservoir_kernel(const float* __restrict__ x,
                      const float* __restrict__ Win,
                      const float* __restrict__ Wfb,
                      const float* __restrict__ bias,
                      float* __restrict__ out)
{
    extern __shared__ float sm[];
    float* Hring = sm;                      // [NSLOT][RDIM] = 21120 f
    float* xs    = Hring + NSLOT * RDIM;    // [SEQ]         = 8192 f
    float* part  = xs + SEQ;                // [320]   part[i*4 + jh]

    const int b   = blockIdx.x;
    const int tid = threadIdx.x;

    for (int idx = tid; idx < NSLOT * RDIM; idx += NTHREADS) Hring[idx] = 0.0f;
    for (int idx = tid; idx < NX; idx += NTHREADS) part[idx] = 0.0f;
    const float* xb = x + (size_t)b * SEQ;
    for (int idx = tid; idx < SEQ; idx += NTHREADS) xs[idx] = xb[idx];

    float* outb = out + (size_t)b * SEQ * RDIM;

    __syncthreads();

    if (tid < NX) {
        // ==================== PRODUCERS (warps 0-9) ====================
        const int xi  = tid % RDIM;         // neuron
        const int xjh = tid / RDIM;         // j-quarter

        // W[0..9] = tau1, W[10..19] = tau4, W[20..29] = tau24,
        // W[30..39] = tau96, W[40..49] = tau168 (20-float slices)
        u64 W[50];
#pragma unroll
        for (int k = 0; k < 5; k++) {
            const float* wrow =
                Wfb + ((size_t)k * RDIM + xi) * RDIM + xjh * 20;
#pragma unroll
            for (int p = 0; p < 10; p++) {
                unsigned lo = __float_as_uint(wrow[2 * p]);
                unsigned hi = __float_as_uint(wrow[2 * p + 1]);
                W[k * 10 + p] = ((u64)hi << 32) | (u64)lo;
            }
        }

        float* ppw = part + xi * 4 + xjh;

        // Prime P1(0): old taps of step 0 (all-zero slots)
        u64 a0 = 0ull, a1 = 0ull, a2 = 0ull, a3 = 0ull;
        {
            const float* q = Hring + xjh * 20;
            TAP_ACC(W + 10, q + 252 * RDIM);
            TAP_ACC(W + 20, q + 232 * RDIM);
            TAP_ACC(W + 30, q + 160 * RDIM);
            TAP_ACC(W + 40, q +  88 * RDIM);
        }

#pragma unroll 1
        for (int T = 0; T < SEQ; T += CHUNK) {
            // Chunk bases; per-step addresses are base + immediate.
            // Offsets reach s+1 <= 8; max base 252 -> 260 <= 263 (mirrors).
            const float* p1b   = Hring + ((unsigned)(T - 1)   & 255u) * RDIM + xjh * 20;
            const float* p4b   = Hring + ((unsigned)(T - 4)   & 255u) * RDIM + xjh * 20;
            const float* p24b  = Hring + ((unsigned)(T - 24)  & 255u) * RDIM + xjh * 20;
            const float* p96b  = Hring + ((unsigned)(T - 96)  & 255u) * RDIM + xjh * 20;
            const float* p168b = Hring + ((unsigned)(T - 168) & 255u) * RDIM + xjh * 20;

#pragma unroll
            for (int s = 0; s < CHUNK; ++s) {
                BAR_SYNC_A();                 // h[t-1] published

                TAP_ACC(W, p1b + s * RDIM);   // tau=1 slice (completes step t)
                float2 r = unpack2(fadd2(fadd2(a0, a1), fadd2(a2, a3)));
                *ppw = r.x + r.y;

                BAR_ARRIVE_B();               // publish partial, don't block

                // P1 for step t+1 (needs h[t-3] and older: long visible)
                a0 = 0ull; a1 = 0ull; a2 = 0ull; a3 = 0ull;
                TAP_ACC(W + 10, p4b   + (s + 1) * RDIM);
                TAP_ACC(W + 20, p24b  + (s + 1) * RDIM);
                TAP_ACC(W + 30, p96b  + (s + 1) * RDIM);
                TAP_ACC(W + 40, p168b + (s + 1) * RDIM);
            }
        }
    } else {
        // ==================== EPILOGUE (warps 10-12) ====================
        const int  yi   = tid - NX;          // 0..95
        const bool yact = yi < RDIM;
        const int  i    = yact ? yi : 0;

        float win_i = 0.0f, bias_i = 0.0f, h_i = 0.0f;
        if (yact) { win_i = Win[i]; bias_i = bias[i]; }

        BAR_ARRIVE_A();                       // priming: h[-1] = 0 valid

#pragma unroll 1
        for (int T = 0; T < SEQ; T += CHUNK) {
            const int  W0     = T & 255;
            float*     hw     = Hring + W0 * RDIM + i;
            const bool mirror = (W0 == 0);
            float*     op     = outb + (size_t)T * RDIM + i;
            const float* xp   = xs + T;

#pragma unroll
            for (int s = 0; s < CHUNK; ++s) {
                float xw = fmaf(xp[s], win_i, bias_i);   // hoisted above sync

                BAR_SYNC_B();                 // partials(t) published

                if (yact) {
                    float4 P = *reinterpret_cast<const float4*>(part + 4 * i);
                    float val = ((P.x + P.y) + (P.z + P.w)) + xw;
                    h_i = 0.7f * h_i + 0.3f * fast_tanh(val);
                    hw[s * RDIM] = h_i;                    // slot W0+s
                    if (mirror) hw[(256 + s) * RDIM] = h_i; // mirrors 256..263
                    op[(size_t)s * RDIM] = h_i;
                }

                BAR_ARRIVE_A();               // publish h[t], don't block
            }
        }
    }
}

extern "C" void kernel_launch(void* const* d_in, const int* in_sizes, int n_in,
                              void* d_out, int out_size)
{
    const float* x    = (const float*)d_in[0];  // [64, 8192, 1]
    const float* Win  = (const float*)d_in[1];  // [80, 1]
    const float* Wfb  = (const float*)d_in[2];  // [5, 80, 80]
    const float* bias = (const float*)d_in[3];  // [80]
    float* out = (float*)d_out;                 // [64, 8192, 80]

    const int smem_bytes = (NSLOT * RDIM + SEQ + NX) * sizeof(float);
    cudaFuncSetAttribute(reservoir_kernel,
                         cudaFuncAttributeMaxDynamicSharedMemorySize, smem_bytes);

    reservoir_kernel<<<BATCH, NTHREADS, smem_bytes>>>(x, Win, Wfb, bias, out);
}